// round 1
// baseline (speedup 1.0000x reference)
#include <cuda_runtime.h>
#include <cstdint>

// ---------------------------------------------------------------------------
// GRU_2602750181500: bidirectional GRU, T=2048, B=32, F=H=512, fp32.
//   out[0]: [T,B,2H]  (reverse direction stored in processing order)
//   out[1]: [1,2,B,H] final states, appended after out[0] if out_size allows.
//
// Kernel 1: gi = x @ w_ih^T + b_ih for both directions (big parallel GEMM).
// Kernel 2: persistent recurrence. 128 blocks = 2 dirs x 4 batch-groups x
//           16 hidden-slices. w_hh slice lives in SMEM for all 2048 steps.
//           Per-step sync only within each 16-block group via monotonic
//           release/acquire flags (graph-replay-safe: flags only grow).
// ---------------------------------------------------------------------------

#define T_ 2048
#define B_ 32
#define H_ 512
#define G_ 1536   // 3*H

typedef unsigned long long ull;

__device__ __forceinline__ ull pkf(float lo, float hi) {
    ull r; asm("mov.b64 %0, {%1, %2};" : "=l"(r) : "f"(lo), "f"(hi)); return r;
}
__device__ __forceinline__ void fma2(ull& d, ull a, ull b) {
    asm("fma.rn.f32x2 %0, %1, %2, %0;" : "+l"(d) : "l"(a), "l"(b));
}
__device__ __forceinline__ float2 upk(ull v) {
    float2 f; asm("mov.b64 {%0, %1}, %2;" : "=f"(f.x), "=f"(f.y) : "l"(v)); return f;
}

// Scratch (device globals: allocation-free rule).
__device__ float    g_gi[2][(size_t)T_ * B_ * G_];   // [dir][t*B+b][3H]
__device__ float    g_h[2][4][2][H_ * 8];            // [dir][bgroup][pingpong][k*8+b]
__device__ unsigned g_flags[2][4][16 * 8];           // [dir][bgroup][slice*8] (padded)

// ---------------------------------------------------------------------------
// Kernel 1: gi GEMM.  C[m][n] = sum_k x[m][k] * w[n][k] + bias[n]
// M = T*B = 65536, N = 1536, K = 512.  128x128 tile, 8x8/thread, f32x2 FMA.
// grid (12, 512, 2), block 256.
// ---------------------------------------------------------------------------
__global__ void __launch_bounds__(256, 2) gi_gemm(
    const float* __restrict__ x,
    const float* __restrict__ wf, const float* __restrict__ bf,
    const float* __restrict__ wr, const float* __restrict__ br)
{
    __shared__ float Xs[8][132];
    __shared__ float Ws[8][132];

    const int tid = threadIdx.x;
    const int dir = blockIdx.z;
    const float* __restrict__ w    = dir ? wr : wf;
    const float* __restrict__ bias = dir ? br : bf;
    float* __restrict__ gi = g_gi[dir];

    const int m0 = blockIdx.y * 128;
    const int n0 = blockIdx.x * 128;

    const int lr = tid >> 1;            // 0..127
    const int lc = (tid & 1) * 4;       // 0 or 4

    const float* xg = x + (size_t)(m0 + lr) * 512 + lc;
    const float* wg = w + (size_t)(n0 + lr) * 512 + lc;

    const int tx = tid & 15, ty = tid >> 4;

    ull acc[8][4];
#pragma unroll
    for (int i = 0; i < 8; i++)
#pragma unroll
        for (int j = 0; j < 4; j++) acc[i][j] = 0ULL;

    float4 xa = *(const float4*)xg;
    float4 wa = *(const float4*)wg;

    for (int kt = 0; kt < 512; kt += 8) {
        Xs[lc + 0][lr] = xa.x; Xs[lc + 1][lr] = xa.y;
        Xs[lc + 2][lr] = xa.z; Xs[lc + 3][lr] = xa.w;
        Ws[lc + 0][lr] = wa.x; Ws[lc + 1][lr] = wa.y;
        Ws[lc + 2][lr] = wa.z; Ws[lc + 3][lr] = wa.w;
        __syncthreads();
        if (kt + 8 < 512) {
            xa = *(const float4*)(xg + kt + 8);
            wa = *(const float4*)(wg + kt + 8);
        }
#pragma unroll
        for (int kk = 0; kk < 8; kk++) {
            float4 a0 = *(const float4*)&Xs[kk][ty * 8];
            float4 a1 = *(const float4*)&Xs[kk][ty * 8 + 4];
            float4 b0 = *(const float4*)&Ws[kk][tx * 8];
            float4 b1 = *(const float4*)&Ws[kk][tx * 8 + 4];
            ull bq[4] = { pkf(b0.x, b0.y), pkf(b0.z, b0.w),
                          pkf(b1.x, b1.y), pkf(b1.z, b1.w) };
            float av[8] = { a0.x, a0.y, a0.z, a0.w, a1.x, a1.y, a1.z, a1.w };
#pragma unroll
            for (int i = 0; i < 8; i++) {
                ull aq = pkf(av[i], av[i]);
#pragma unroll
                for (int j = 0; j < 4; j++) fma2(acc[i][j], aq, bq[j]);
            }
        }
        __syncthreads();
    }

    float bb2[8];
#pragma unroll
    for (int j = 0; j < 8; j++) bb2[j] = bias[n0 + tx * 8 + j];
#pragma unroll
    for (int i = 0; i < 8; i++) {
        float* cp = gi + (size_t)(m0 + ty * 8 + i) * G_ + n0 + tx * 8;
#pragma unroll
        for (int j = 0; j < 4; j++) {
            float2 v = upk(acc[i][j]);
            v.x += bb2[2 * j]; v.y += bb2[2 * j + 1];
            *(float2*)(cp + 2 * j) = v;
        }
    }
}

// ---------------------------------------------------------------------------
// Kernel 2: persistent recurrence.
// grid 128 (= 2 dirs * 4 bgroups * 16 slices), block 256.
// Per block: 8 batches (bgroup), 32 hidden units (slice) -> 96 w_hh rows in
// SMEM (stride 513 to kill bank conflicts). h for the 8 batches ping-pongs
// through global (L2), layout [k][8].
// ---------------------------------------------------------------------------
#define SMEM_W   (96 * 513)
#define SMEM_H   (512 * 8)
#define SMEM_GH  (96 * 12)
#define SMEM_REC ((SMEM_W + SMEM_H + SMEM_GH) * 4)

__global__ void __launch_bounds__(256, 1) gru_rec(
    const float* __restrict__ h0,
    const float* __restrict__ whh_f, const float* __restrict__ bhh_f,
    const float* __restrict__ whh_r, const float* __restrict__ bhh_r,
    float* __restrict__ out, int out_size)
{
    extern __shared__ float smem[];
    float* sw  = smem;                  // [96][513]
    float* sh  = smem + SMEM_W;         // [512][8]
    float* sgh = sh + SMEM_H;           // [96][12]

    const int tid = threadIdx.x;
    const int bid = blockIdx.x;
    const int dir = bid >> 6;
    const int g6  = bid & 63;
    const int bg  = g6 >> 4;   // batch group 0..3
    const int sl  = g6 & 15;   // hidden slice 0..15

    const float* __restrict__ whh = dir ? whh_r : whh_f;
    const float* __restrict__ bhh = dir ? bhh_r : bhh_f;
    const float* __restrict__ gi  = g_gi[dir];
    volatile unsigned* flags = &g_flags[dir][bg][0];
    const unsigned base = flags[sl * 8];

    // Load 96 w_hh rows into SMEM (one time).
    for (int idx = tid; idx < 96 * 128; idx += 256) {
        int r = idx >> 7, c4 = (idx & 127) << 2;
        int gate = r >> 5, il2 = r & 31;
        float4 v = *(const float4*)&whh[(size_t)((gate << 9) + sl * 32 + il2) * 512 + c4];
        float* d = &sw[r * 513 + c4];
        d[0] = v.x; d[1] = v.y; d[2] = v.z; d[3] = v.w;
    }

    // Epilogue thread mapping: b = tid>>5 (0..7 within group), il = tid&31.
    const int b  = tid >> 5;
    const int il = tid & 31;
    const int iglob = sl * 32 + il;
    const int bglob = bg * 8 + b;

    float* hbuf0 = g_h[dir][bg][0];
    float* hbuf1 = g_h[dir][bg][1];

    // h init from h0 (this block's 32x8 chunk).
    hbuf0[iglob * 8 + b] = h0[(size_t)(dir * B_ + bglob) * H_ + iglob];

    const float bh_r = bhh[iglob];
    const float bh_z = bhh[512 + iglob];
    const float bh_n = bhh[1024 + iglob];

    __syncthreads();
    __threadfence();
    if (tid == 0) flags[sl * 8] = base + 1;

    // k-loop mapping (192 active threads): kr = row 0..95, bpq = batch quad.
    const int kr  = tid >> 1;
    const int bpq = tid & 1;

    const bool write_states = (out_size > T_ * B_ * 2 * H_);

    for (int s = 0; s < T_; s++) {
        // Acquire: wait until all 16 slice blocks published h for this step.
        if (tid < 16) {
            const unsigned target = base + 1 + (unsigned)s;
            while (flags[tid * 8] < target) __nanosleep(40);
        }
        __syncthreads();
        __threadfence();

        const float* hsrc = (s & 1) ? hbuf1 : hbuf0;
        float*       hdst = (s & 1) ? hbuf0 : hbuf1;

        // Load full h (512 x 8) into SMEM, L1-bypassed (written by other SMs).
        for (int idx = tid; idx < 1024; idx += 256)
            *(float4*)&sh[idx * 4] = __ldcg((const float4*)hsrc + idx);
        __syncthreads();

        // gh = h @ w_hh_slice^T  (96 rows x 8 batches)
        if (tid < 192) {
            ull acc0 = 0ULL, acc1 = 0ULL;
            const float* wr_ = &sw[kr * 513];
            const float4* hv = (const float4*)sh;
#pragma unroll 8
            for (int k = 0; k < 512; k++) {
                float wv = wr_[k];
                ull wq = pkf(wv, wv);
                float4 h4 = hv[k * 2 + bpq];
                fma2(acc0, wq, pkf(h4.x, h4.y));
                fma2(acc1, wq, pkf(h4.z, h4.w));
            }
            float2 p0 = upk(acc0), p1 = upk(acc1);
            *(float4*)&sgh[kr * 12 + bpq * 4] = make_float4(p0.x, p0.y, p1.x, p1.y);
        }
        __syncthreads();

        // Gates + state update.
        const int xrow = dir ? (T_ - 1 - s) : s;
        const float* gp = gi + ((size_t)xrow * B_ + bglob) * G_ + iglob;
        const float gir = __ldcs(gp);
        const float giz = __ldcs(gp + 512);
        const float gin = __ldcs(gp + 1024);

        const float ghr = sgh[il * 12 + b]        + bh_r;
        const float ghz = sgh[(32 + il) * 12 + b] + bh_z;
        const float ghn = sgh[(64 + il) * 12 + b] + bh_n;
        const float hold = sh[iglob * 8 + b];

        const float rg = 1.f / (1.f + __expf(-(gir + ghr)));
        const float zg = 1.f / (1.f + __expf(-(giz + ghz)));
        const float ng = tanhf(gin + rg * ghn);
        const float hn = (1.f - zg) * ng + zg * hold;

        out[((size_t)s * B_ + bglob) * (2 * H_) + dir * H_ + iglob] = hn;
        __stcg(&hdst[iglob * 8 + b], hn);
        if (write_states && s == T_ - 1)
            out[(size_t)T_ * B_ * 2 * H_ + (size_t)(dir * B_ + bglob) * H_ + iglob] = hn;

        // Release: publish h(s+1).
        __syncthreads();
        __threadfence();
        if (tid == 0) flags[sl * 8] = base + 2 + (unsigned)s;
    }
}

// ---------------------------------------------------------------------------
extern "C" void kernel_launch(void* const* d_in, const int* in_sizes, int n_in,
                              void* d_out, int out_size)
{
    const float* x    = (const float*)d_in[0];
    const float* h0   = (const float*)d_in[1];
    const float* wihf = (const float*)d_in[2];
    const float* bihf = (const float*)d_in[3];
    const float* whhf = (const float*)d_in[4];
    const float* bhhf = (const float*)d_in[5];
    const float* wihr = (const float*)d_in[6];
    const float* bihr = (const float*)d_in[7];
    const float* whhr = (const float*)d_in[8];
    const float* bhhr = (const float*)d_in[9];
    float* out = (float*)d_out;

    cudaFuncSetAttribute(gru_rec, cudaFuncAttributeMaxDynamicSharedMemorySize, SMEM_REC);

    dim3 g1(G_ / 128, (T_ * B_) / 128, 2);   // (12, 512, 2)
    gi_gemm<<<g1, 256>>>(x, wihf, bihf, wihr, bihr);

    gru_rec<<<128, 256, SMEM_REC>>>(h0, whhf, bhhf, whhr, bhhr, out, out_size);
}